// round 4
// baseline (speedup 1.0000x reference)
#include <cuda_runtime.h>
#include <cuda_bf16.h>
#include <cstdint>

// ---------------------------------------------------------------------------
// MultiAxisAttention (Swin window attention) — HMMA tf32 pipeline (sm_103,
// baseline PTX only: harness emits compute_103 PTX, tcgen05 unavailable).
//   prep: xr = rna(x) (padded rows zeroed), w_qkv/w_out rna-rounded in place
//   K1:   qkv = xr @ wqkv_r     (tf32 mma, cp.async double-buffer)
//   K2:   per-(window,head) 49x49 softmax attention -> att (tf32-rounded)
//   K3:   out = att @ wout_r
// ---------------------------------------------------------------------------

#define M_REAL 153664            // 16*196*49
#define M_PAD  153728            // 1201*128
#define NWIN   3136
#define HEADS  16
#define DH     32
#define WIN    49
#define KDIM   512

__device__ float g_qkv[236027904];    // M_REAL*1536
__device__ float g_att[78708736];     // M_PAD*512 (pad rows zeroed)
__device__ float g_xr [78708736];     // M_PAD*512 (tf32-rounded, pad zeroed)
__device__ float g_wqkv_r[786432];    // 512*1536 rounded
__device__ float g_wout_r[262144];    // 512*512  rounded

// ------------------------------ helpers -----------------------------------
__device__ __forceinline__ float tf32r(float f) {
    unsigned u;
    asm("cvt.rna.tf32.f32 %0, %1;" : "=r"(u) : "f"(f));
    return __uint_as_float(u);
}
__device__ __forceinline__ uint32_t smem_u32(const void* p) {
    uint32_t a;
    asm("{ .reg .u64 t; cvta.to.shared.u64 t, %1; cvt.u32.u64 %0, t; }"
        : "=r"(a) : "l"(p));
    return a;
}
__device__ __forceinline__ void cp16(uint32_t dst, const void* src) {
    asm volatile("cp.async.cg.shared.global [%0], [%1], 16;\n"
                 :: "r"(dst), "l"(src));
}
#define CP_COMMIT() asm volatile("cp.async.commit_group;\n" ::: "memory")
#define CP_WAIT(n)  asm volatile("cp.async.wait_group %0;\n" :: "n"(n) : "memory")

__device__ __forceinline__ void mma_tf32(float* d, const unsigned* a, const unsigned* b) {
    asm volatile(
        "mma.sync.aligned.m16n8k8.row.col.f32.tf32.tf32.f32 "
        "{%0,%1,%2,%3}, {%4,%5,%6,%7}, {%8,%9}, {%0,%1,%2,%3};\n"
        : "+f"(d[0]), "+f"(d[1]), "+f"(d[2]), "+f"(d[3])
        : "r"(a[0]), "r"(a[1]), "r"(a[2]), "r"(a[3]),
          "r"(b[0]), "r"(b[1]));
}

__device__ __forceinline__ unsigned long long pk2(float a, float b) {
    unsigned long long r;
    asm("mov.b64 %0, {%1, %2};" : "=l"(r) : "f"(a), "f"(b));
    return r;
}
__device__ __forceinline__ void fma2(unsigned long long& d,
                                     unsigned long long a, unsigned long long b) {
    asm("fma.rn.f32x2 %0, %1, %2, %0;" : "+l"(d) : "l"(a), "l"(b));
}
__device__ __forceinline__ void unpk2(float& a, float& b, unsigned long long r) {
    asm("mov.b64 {%0, %1}, %2;" : "=f"(a), "=f"(b) : "l"(r));
}

// ------------------------------- GEMM (tf32) ------------------------------
// block 128x128, BK=32, 4 warps (2x2), warp tile 64x64, cp.async dbl-buffer.
// Inputs must be tf32-pre-rounded. A: [M,512] row-major. B: [512,N] row-major.
#define BM 128
#define BN 128
#define BK 32
#define AST 36    // As row stride (BK+4): frag banks 4*grp+tg -> conflict-free
#define BST 136   // Bs row stride (BN+8): frag banks 8*tg+grp -> conflict-free
#define AS_FLOATS (BM * AST)          // 4608
#define BS_FLOATS (BK * BST)          // 4352
#define SMEM_FLOATS (2 * AS_FLOATS + 2 * BS_FLOATS)   // 17920 -> 71680 B

__global__ void __launch_bounds__(128)
gemm_tf32(const float* __restrict__ A, const float* __restrict__ B,
          float* __restrict__ C, int Mreal, int N)
{
    extern __shared__ float sm[];
    float* As = sm;                       // [2][AS_FLOATS]
    float* Bs = sm + 2 * AS_FLOATS;       // [2][BS_FLOATS]

    const int tid  = threadIdx.x;
    const int lane = tid & 31;
    const int warp = tid >> 5;          // 0..3
    const int wm   = warp >> 1;
    const int wn   = warp & 1;
    const int grp  = lane >> 2;         // 0..7
    const int tg   = lane & 3;          // 0..3

    const int m0 = blockIdx.y * BM;
    const int n0 = blockIdx.x * BN;

    // A fill: thread owns row tid, 8 x 16B (BK=32 floats)
    const float* agp = A + (size_t)(m0 + tid) * KDIM;
    const uint32_t a_dst0 = smem_u32(As) + (uint32_t)(tid * AST) * 4;
    // B fill: thread owns row (tid>>2), cols (tid&3)*32 .. +32
    const int brow = tid >> 2;
    const int bcol = (tid & 3) << 5;
    const uint32_t b_dst0 = smem_u32(Bs) + (uint32_t)(brow * BST + bcol) * 4;
    const float* bgp = B + (size_t)brow * N + n0 + bcol;

    float acc[4][8][4];
    #pragma unroll
    for (int i = 0; i < 4; i++)
        #pragma unroll
        for (int j = 0; j < 8; j++)
            #pragma unroll
            for (int l = 0; l < 4; l++) acc[i][j][l] = 0.f;

    const int T = KDIM / BK;   // 16

    // prologue: stage 0 -> buffer 0
    #pragma unroll
    for (int c = 0; c < 8; c++) cp16(a_dst0 + c * 16, agp + c * 4);
    #pragma unroll
    for (int c = 0; c < 8; c++) cp16(b_dst0 + c * 16, bgp + c * 4);
    CP_COMMIT();

    for (int t = 0; t < T; ++t) {
        const int buf = t & 1;

        if (t + 1 < T) {
            const int nb = (t + 1) & 1;
            const uint32_t ad = a_dst0 + (uint32_t)nb * AS_FLOATS * 4;
            const uint32_t bd = b_dst0 + (uint32_t)nb * BS_FLOATS * 4;
            const float* ag = agp + (t + 1) * BK;
            const float* bg = bgp + (size_t)(t + 1) * BK * N;
            #pragma unroll
            for (int c = 0; c < 8; c++) cp16(ad + c * 16, ag + c * 4);
            #pragma unroll
            for (int c = 0; c < 8; c++) cp16(bd + c * 16, bg + c * 4);
            CP_COMMIT();
            CP_WAIT(1);
        } else {
            CP_WAIT(0);
        }
        __syncthreads();

        const float* Ab = As + buf * AS_FLOATS;
        const float* Bb = Bs + buf * BS_FLOATS;
        #pragma unroll
        for (int ks = 0; ks < 4; ks++) {
            const int kk = ks * 8;
            unsigned af[4][4], bf[8][2];
            #pragma unroll
            for (int mt = 0; mt < 4; mt++) {
                int mr = wm * 64 + mt * 16 + grp;
                af[mt][0] = __float_as_uint(Ab[ mr      * AST + kk + tg]);
                af[mt][1] = __float_as_uint(Ab[(mr + 8) * AST + kk + tg]);
                af[mt][2] = __float_as_uint(Ab[ mr      * AST + kk + tg + 4]);
                af[mt][3] = __float_as_uint(Ab[(mr + 8) * AST + kk + tg + 4]);
            }
            #pragma unroll
            for (int nt = 0; nt < 8; nt++) {
                int nc = wn * 64 + nt * 8 + grp;
                bf[nt][0] = __float_as_uint(Bb[(kk + tg)     * BST + nc]);
                bf[nt][1] = __float_as_uint(Bb[(kk + tg + 4) * BST + nc]);
            }
            #pragma unroll
            for (int mt = 0; mt < 4; mt++)
                #pragma unroll
                for (int nt = 0; nt < 8; nt++)
                    mma_tf32(acc[mt][nt], af[mt], bf[nt]);
        }
        __syncthreads();
    }

    // epilogue
    #pragma unroll
    for (int mt = 0; mt < 4; mt++) {
        #pragma unroll
        for (int nt = 0; nt < 8; nt++) {
            int r0 = m0 + wm * 64 + mt * 16 + grp;
            int c  = n0 + wn * 64 + nt * 8 + tg * 2;
            if (r0 < Mreal)
                *(float2*)(C + (size_t)r0 * N + c) =
                    make_float2(acc[mt][nt][0], acc[mt][nt][1]);
            if (r0 + 8 < Mreal)
                *(float2*)(C + (size_t)(r0 + 8) * N + c) =
                    make_float2(acc[mt][nt][2], acc[mt][nt][3]);
        }
    }
}

// ------------------------------ prep kernels -------------------------------
__global__ void round_pad(const float* __restrict__ x, float* __restrict__ xr,
                          long nreal, long ntot)
{
    long i = (long)blockIdx.x * blockDim.x + threadIdx.x;
    if (i < ntot) xr[i] = (i < nreal) ? tf32r(x[i]) : 0.f;
}

__global__ void round_copy(const float* __restrict__ w, float* __restrict__ wr, int n)
{
    int i = blockIdx.x * blockDim.x + threadIdx.x;
    if (i < n) wr[i] = tf32r(w[i]);
}

__global__ void zero_fill(float* __restrict__ p, int n)
{
    int i = blockIdx.x * blockDim.x + threadIdx.x;
    if (i < n) p[i] = 0.f;
}

// ----------------------------- attention kernel ----------------------------
// one CTA per (window, head); 64 threads; thread r (<49) owns query row r.
__global__ void __launch_bounds__(64)
attn_kernel(const float* __restrict__ qkv,
            const float* __restrict__ bias_table,
            float* __restrict__ out)
{
    const int h  = blockIdx.x & 15;
    const int bw = blockIdx.x >> 4;

    __shared__ float4 Ks4[WIN * 8];
    __shared__ float4 Vs4[WIN * 8];
    __shared__ float4 Os4[WIN * 8];
    __shared__ float4 pool4[625];        // Q [49][9] f4, then scores [49][51] f32
    __shared__ float  bs[169];

    const int tid = threadIdx.x;
    const float* base = qkv + (size_t)bw * WIN * 1536 + h * DH;
    const float SCALE = 0.17677669529663687f;

    for (int l = tid; l < WIN * 8; l += 64) {
        int i = l >> 3, c = l & 7;
        const float4* row = (const float4*)(base + (size_t)i * 1536);
        float4 qv = row[c];
        qv.x *= SCALE; qv.y *= SCALE; qv.z *= SCALE; qv.w *= SCALE;
        pool4[i * 9 + c] = qv;
        Ks4[i * 8 + c] = *((const float4*)(base + (size_t)i * 1536 + 512) + c);
        Vs4[i * 8 + c] = *((const float4*)(base + (size_t)i * 1536 + 1024) + c);
    }
    for (int l = tid; l < 169; l += 64) bs[l] = bias_table[l * HEADS + h];
    __syncthreads();

    unsigned long long q2[16];
    if (tid < WIN) {
        #pragma unroll
        for (int c = 0; c < 8; c++) {
            float4 qv = pool4[tid * 9 + c];
            q2[2 * c]     = pk2(qv.x, qv.y);
            q2[2 * c + 1] = pk2(qv.z, qv.w);
        }
    }
    __syncthreads();

    float* Ss = (float*)pool4;
    if (tid < WIN) {
        const int ri = tid / 7, ci = tid % 7;
        float sum = 0.f;
        for (int rj = 0; rj < 7; rj++) {
            #pragma unroll
            for (int cj = 0; cj < 7; cj++) {
                const int j = rj * 7 + cj;
                unsigned long long s2 = 0ull;
                #pragma unroll
                for (int c = 0; c < 8; c++) {
                    float4 kv = Ks4[j * 8 + c];
                    fma2(s2, q2[2 * c],     pk2(kv.x, kv.y));
                    fma2(s2, q2[2 * c + 1], pk2(kv.z, kv.w));
                }
                float lo, hi; unpk2(lo, hi, s2);
                float s = lo + hi + bs[(ri - rj + 6) * 13 + (ci - cj + 6)];
                float e = __expf(s);
                Ss[tid * 51 + j] = e;
                sum += e;
            }
        }
        const float inv = 1.f / sum;

        unsigned long long o2[16];
        #pragma unroll
        for (int c = 0; c < 16; c++) o2[c] = 0ull;
        for (int j = 0; j < WIN; j++) {
            float p = Ss[tid * 51 + j] * inv;
            unsigned long long p2 = pk2(p, p);
            #pragma unroll
            for (int c = 0; c < 8; c++) {
                float4 vv = Vs4[j * 8 + c];
                fma2(o2[2 * c],     p2, pk2(vv.x, vv.y));
                fma2(o2[2 * c + 1], p2, pk2(vv.z, vv.w));
            }
        }
        #pragma unroll
        for (int c = 0; c < 8; c++) {
            float4 ov;
            unpk2(ov.x, ov.y, o2[2 * c]);
            unpk2(ov.z, ov.w, o2[2 * c + 1]);
            // tf32-round here so K3 consumes pre-rounded A with no cvt
            ov.x = tf32r(ov.x); ov.y = tf32r(ov.y);
            ov.z = tf32r(ov.z); ov.w = tf32r(ov.w);
            Os4[tid * 8 + c] = ov;
        }
    }
    __syncthreads();

    float* obase = out + (size_t)bw * WIN * 512 + h * DH;
    for (int l = tid; l < WIN * 8; l += 64) {
        int i = l >> 3, c = l & 7;
        *((float4*)(obase + (size_t)i * 512) + c) = Os4[i * 8 + c];
    }
}

// --------------------------------- launcher --------------------------------
extern "C" void kernel_launch(void* const* d_in, const int* in_sizes, int n_in,
                              void* d_out, int out_size)
{
    const float* x          = (const float*)d_in[0];
    const float* w_qkv      = (const float*)d_in[1];
    const float* bias_table = (const float*)d_in[2];
    const float* w_out      = (const float*)d_in[3];
    float* out = (float*)d_out;

    float *qkv, *att, *xr, *wqkv_r, *wout_r;
    cudaGetSymbolAddress((void**)&qkv,    g_qkv);
    cudaGetSymbolAddress((void**)&att,    g_att);
    cudaGetSymbolAddress((void**)&xr,     g_xr);
    cudaGetSymbolAddress((void**)&wqkv_r, g_wqkv_r);
    cudaGetSymbolAddress((void**)&wout_r, g_wout_r);

    cudaFuncSetAttribute(gemm_tf32, cudaFuncAttributeMaxDynamicSharedMemorySize,
                         SMEM_FLOATS * 4);

    const long nreal = (long)M_REAL * 512;
    const long ntot  = (long)M_PAD  * 512;

    round_pad<<<(int)((ntot + 255) / 256), 256>>>(x, xr, nreal, ntot);
    round_copy<<<(786432 + 255) / 256, 256>>>(w_qkv, wqkv_r, 786432);
    round_copy<<<(262144 + 255) / 256, 256>>>(w_out, wout_r, 262144);
    zero_fill<<<(64 * 512 + 255) / 256, 256>>>(att + nreal, 64 * 512);

    // K1: qkv = xr @ wqkv_r
    gemm_tf32<<<dim3(1536 / BN, M_PAD / BM), 128, SMEM_FLOATS * 4>>>(
        xr, wqkv_r, qkv, M_REAL, 1536);

    // K2: attention
    attn_kernel<<<NWIN * HEADS, 64>>>(qkv, bias_table, att);

    // K3: out = att @ wout_r
    gemm_tf32<<<dim3(512 / BN, M_PAD / BM), 128, SMEM_FLOATS * 4>>>(
        att, wout_r, out, M_REAL, 512);
}

// round 5
// speedup vs baseline: 1.6146x; 1.6146x over previous
#include <cuda_runtime.h>
#include <cuda_bf16.h>
#include <cstdint>

// ---------------------------------------------------------------------------
// MultiAxisAttention (Swin window attention) — HMMA tf32 pipeline (sm_103
// baseline PTX; tcgen05 not available in this toolchain path).
//   prep: xr = rna(x) (pad rows zeroed), weights rna-rounded
//   K1:   qkv = xr @ wqkv_r     (tf32 mma, cp.async dbl-buffer, coalesced)
//   K2:   per-(window,head) 49x49 softmax attention -> att (tf32-rounded)
//   K3:   out = att @ wout_r
// ---------------------------------------------------------------------------

#define M_REAL 153664            // 16*196*49
#define M_PAD  153728            // 1201*128
#define NWIN   3136
#define HEADS  16
#define DH     32
#define WIN    49
#define KDIM   512

__device__ float g_qkv[236027904];    // M_REAL*1536
__device__ float g_att[78708736];     // M_PAD*512 (pad rows zeroed)
__device__ float g_xr [78708736];     // M_PAD*512 (tf32-rounded, pad zeroed)
__device__ float g_wqkv_r[786432];    // 512*1536 rounded
__device__ float g_wout_r[262144];    // 512*512  rounded

// ------------------------------ helpers -----------------------------------
__device__ __forceinline__ float tf32r(float f) {
    unsigned u;
    asm("cvt.rna.tf32.f32 %0, %1;" : "=r"(u) : "f"(f));
    return __uint_as_float(u);
}
__device__ __forceinline__ uint32_t smem_u32(const void* p) {
    uint32_t a;
    asm("{ .reg .u64 t; cvta.to.shared.u64 t, %1; cvt.u32.u64 %0, t; }"
        : "=r"(a) : "l"(p));
    return a;
}
__device__ __forceinline__ void cp16(uint32_t dst, const void* src) {
    asm volatile("cp.async.cg.shared.global [%0], [%1], 16;\n"
                 :: "r"(dst), "l"(src));
}
#define CP_COMMIT() asm volatile("cp.async.commit_group;\n" ::: "memory")
#define CP_WAIT(n)  asm volatile("cp.async.wait_group %0;\n" :: "n"(n) : "memory")

__device__ __forceinline__ void mma_tf32(float* d, const unsigned* a, const unsigned* b) {
    asm volatile(
        "mma.sync.aligned.m16n8k8.row.col.f32.tf32.tf32.f32 "
        "{%0,%1,%2,%3}, {%4,%5,%6,%7}, {%8,%9}, {%0,%1,%2,%3};\n"
        : "+f"(d[0]), "+f"(d[1]), "+f"(d[2]), "+f"(d[3])
        : "r"(a[0]), "r"(a[1]), "r"(a[2]), "r"(a[3]),
          "r"(b[0]), "r"(b[1]));
}

__device__ __forceinline__ unsigned long long pk2(float a, float b) {
    unsigned long long r;
    asm("mov.b64 %0, {%1, %2};" : "=l"(r) : "f"(a), "f"(b));
    return r;
}
__device__ __forceinline__ void fma2(unsigned long long& d,
                                     unsigned long long a, unsigned long long b) {
    asm("fma.rn.f32x2 %0, %1, %2, %0;" : "+l"(d) : "l"(a), "l"(b));
}
__device__ __forceinline__ void unpk2(float& a, float& b, unsigned long long r) {
    asm("mov.b64 {%0, %1}, %2;" : "=f"(a), "=f"(b) : "l"(r));
}

// ------------------------------- GEMM (tf32) ------------------------------
// block 128x128, BK=32, 4 warps (2x2), warp tile 64x64, cp.async dbl-buffer.
// Inputs tf32-pre-rounded. A: [M,512] row-major. B: [512,N] row-major.
// Fill mapping is warp-coalesced: 4 gmem lines per LDGSTS instruction.
#define BM 128
#define BN 128
#define BK 32
#define AST 36    // As row stride (BK+4): frag banks 4*grp+tg -> conflict-free
#define BST 136   // Bs row stride (BN+8): frag banks 8*tg+grp -> conflict-free
#define AS_FLOATS (BM * AST)          // 4608
#define BS_FLOATS (BK * BST)          // 4352
#define SMEM_FLOATS (2 * AS_FLOATS + 2 * BS_FLOATS)   // 17920 -> 71680 B

__global__ void __launch_bounds__(128)
gemm_tf32(const float* __restrict__ A, const float* __restrict__ B,
          float* __restrict__ C, int Mreal, int N)
{
    extern __shared__ float sm[];
    float* As = sm;                       // [2][AS_FLOATS]
    float* Bs = sm + 2 * AS_FLOATS;       // [2][BS_FLOATS]

    const int tid  = threadIdx.x;
    const int lane = tid & 31;
    const int warp = tid >> 5;          // 0..3
    const int wm   = warp >> 1;
    const int wn   = warp & 1;
    const int grp  = lane >> 2;         // 0..7
    const int tg   = lane & 3;          // 0..3

    const int m0 = blockIdx.y * BM;
    const int n0 = blockIdx.x * BN;

    // --- coalesced fill geometry ---
    // A: warp covers 4 rows x 128B; thread = (row = p*16 + tid>>3, chunk = tid&7)
    const int arow = tid >> 3;             // 0..15
    const int achk = (tid & 7) << 2;       // float offset 0,4,..,28
    const float*  ag0  = A + (size_t)(m0 + arow) * KDIM + achk;
    const uint32_t asm0 = smem_u32(As) + (uint32_t)(arow * AST + achk) * 4;
    // B: warp covers one row's 512B; thread = (row = p*4 + tid>>5, chunk = tid&31)
    const int brow = tid >> 5;             // 0..3
    const int bchk = (tid & 31) << 2;      // 0..124
    const float*  bg0  = B + (size_t)brow * N + n0 + bchk;
    const uint32_t bsm0 = smem_u32(Bs) + (uint32_t)(brow * BST + bchk) * 4;

    float acc[4][8][4];
    #pragma unroll
    for (int i = 0; i < 4; i++)
        #pragma unroll
        for (int j = 0; j < 8; j++)
            #pragma unroll
            for (int l = 0; l < 4; l++) acc[i][j][l] = 0.f;

    const int T = KDIM / BK;   // 16

    // prologue: stage 0 -> buffer 0
    #pragma unroll
    for (int p = 0; p < 8; p++)
        cp16(asm0 + (uint32_t)(p * 16 * AST) * 4, ag0 + (size_t)p * 16 * KDIM);
    #pragma unroll
    for (int p = 0; p < 8; p++)
        cp16(bsm0 + (uint32_t)(p * 4 * BST) * 4, bg0 + (size_t)p * 4 * N);
    CP_COMMIT();

    for (int t = 0; t < T; ++t) {
        const int buf = t & 1;

        if (t + 1 < T) {
            const int nb = (t + 1) & 1;
            const int kb = (t + 1) * BK;
            const uint32_t ad = asm0 + (uint32_t)nb * AS_FLOATS * 4;
            const uint32_t bd = bsm0 + (uint32_t)nb * BS_FLOATS * 4;
            const float* ag = ag0 + kb;
            const float* bg = bg0 + (size_t)kb * N;
            #pragma unroll
            for (int p = 0; p < 8; p++)
                cp16(ad + (uint32_t)(p * 16 * AST) * 4, ag + (size_t)p * 16 * KDIM);
            #pragma unroll
            for (int p = 0; p < 8; p++)
                cp16(bd + (uint32_t)(p * 4 * BST) * 4, bg + (size_t)p * 4 * N);
            CP_COMMIT();
            CP_WAIT(1);
        } else {
            CP_WAIT(0);
        }
        __syncthreads();

        const float* Ab = As + buf * AS_FLOATS;
        const float* Bb = Bs + buf * BS_FLOATS;
        #pragma unroll
        for (int ks = 0; ks < 4; ks++) {
            const int kk = ks * 8;
            unsigned af[4][4], bf[8][2];
            #pragma unroll
            for (int mt = 0; mt < 4; mt++) {
                int mr = wm * 64 + mt * 16 + grp;
                af[mt][0] = __float_as_uint(Ab[ mr      * AST + kk + tg]);
                af[mt][1] = __float_as_uint(Ab[(mr + 8) * AST + kk + tg]);
                af[mt][2] = __float_as_uint(Ab[ mr      * AST + kk + tg + 4]);
                af[mt][3] = __float_as_uint(Ab[(mr + 8) * AST + kk + tg + 4]);
            }
            #pragma unroll
            for (int nt = 0; nt < 8; nt++) {
                int nc = wn * 64 + nt * 8 + grp;
                bf[nt][0] = __float_as_uint(Bb[(kk + tg)     * BST + nc]);
                bf[nt][1] = __float_as_uint(Bb[(kk + tg + 4) * BST + nc]);
            }
            #pragma unroll
            for (int mt = 0; mt < 4; mt++)
                #pragma unroll
                for (int nt = 0; nt < 8; nt++)
                    mma_tf32(acc[mt][nt], af[mt], bf[nt]);
        }
        __syncthreads();
    }

    // epilogue
    #pragma unroll
    for (int mt = 0; mt < 4; mt++) {
        #pragma unroll
        for (int nt = 0; nt < 8; nt++) {
            int r0 = m0 + wm * 64 + mt * 16 + grp;
            int c  = n0 + wn * 64 + nt * 8 + tg * 2;
            if (r0 < Mreal)
                *(float2*)(C + (size_t)r0 * N + c) =
                    make_float2(acc[mt][nt][0], acc[mt][nt][1]);
            if (r0 + 8 < Mreal)
                *(float2*)(C + (size_t)(r0 + 8) * N + c) =
                    make_float2(acc[mt][nt][2], acc[mt][nt][3]);
        }
    }
}

// ------------------------------ prep kernels -------------------------------
__global__ void round_pad(const float* __restrict__ x, float* __restrict__ xr,
                          long nreal, long ntot)
{
    long i = (long)blockIdx.x * blockDim.x + threadIdx.x;
    if (i < ntot) xr[i] = (i < nreal) ? tf32r(x[i]) : 0.f;
}

__global__ void round_copy(const float* __restrict__ w, float* __restrict__ wr, int n)
{
    int i = blockIdx.x * blockDim.x + threadIdx.x;
    if (i < n) wr[i] = tf32r(w[i]);
}

__global__ void zero_fill(float* __restrict__ p, int n)
{
    int i = blockIdx.x * blockDim.x + threadIdx.x;
    if (i < n) p[i] = 0.f;
}

// ----------------------------- attention kernel ----------------------------
// one CTA per (window, head); 64 threads; thread r (<49) owns query row r.
__global__ void __launch_bounds__(64)
attn_kernel(const float* __restrict__ qkv,
            const float* __restrict__ bias_table,
            float* __restrict__ out)
{
    const int h  = blockIdx.x & 15;
    const int bw = blockIdx.x >> 4;

    __shared__ float4 Ks4[WIN * 8];
    __shared__ float4 Vs4[WIN * 8];
    __shared__ float4 Os4[WIN * 8];
    __shared__ float4 pool4[625];        // Q [49][9] f4, then scores [49][51] f32
    __shared__ float  bs[169];

    const int tid = threadIdx.x;
    const float* base = qkv + (size_t)bw * WIN * 1536 + h * DH;
    const float SCALE = 0.17677669529663687f;

    for (int l = tid; l < WIN * 8; l += 64) {
        int i = l >> 3, c = l & 7;
        const float4* row = (const float4*)(base + (size_t)i * 1536);
        float4 qv = row[c];
        qv.x *= SCALE; qv.y *= SCALE; qv.z *= SCALE; qv.w *= SCALE;
        pool4[i * 9 + c] = qv;
        Ks4[i * 8 + c] = *((const float4*)(base + (size_t)i * 1536 + 512) + c);
        Vs4[i * 8 + c] = *((const float4*)(base + (size_t)i * 1536 + 1024) + c);
    }
    for (int l = tid; l < 169; l += 64) bs[l] = bias_table[l * HEADS + h];
    __syncthreads();

    unsigned long long q2[16];
    if (tid < WIN) {
        #pragma unroll
        for (int c = 0; c < 8; c++) {
            float4 qv = pool4[tid * 9 + c];
            q2[2 * c]     = pk2(qv.x, qv.y);
            q2[2 * c + 1] = pk2(qv.z, qv.w);
        }
    }
    __syncthreads();

    float* Ss = (float*)pool4;
    if (tid < WIN) {
        const int ri = tid / 7, ci = tid % 7;
        float sum = 0.f;
        for (int rj = 0; rj < 7; rj++) {
            #pragma unroll
            for (int cj = 0; cj < 7; cj++) {
                const int j = rj * 7 + cj;
                unsigned long long s2 = 0ull;
                #pragma unroll
                for (int c = 0; c < 8; c++) {
                    float4 kv = Ks4[j * 8 + c];
                    fma2(s2, q2[2 * c],     pk2(kv.x, kv.y));
                    fma2(s2, q2[2 * c + 1], pk2(kv.z, kv.w));
                }
                float lo, hi; unpk2(lo, hi, s2);
                float s = lo + hi + bs[(ri - rj + 6) * 13 + (ci - cj + 6)];
                float e = __expf(s);
                Ss[tid * 51 + j] = e;
                sum += e;
            }
        }
        const float inv = 1.f / sum;

        unsigned long long o2[16];
        #pragma unroll
        for (int c = 0; c < 16; c++) o2[c] = 0ull;
        for (int j = 0; j < WIN; j++) {
            float p = Ss[tid * 51 + j] * inv;
            unsigned long long p2 = pk2(p, p);
            #pragma unroll
            for (int c = 0; c < 8; c++) {
                float4 vv = Vs4[j * 8 + c];
                fma2(o2[2 * c],     p2, pk2(vv.x, vv.y));
                fma2(o2[2 * c + 1], p2, pk2(vv.z, vv.w));
            }
        }
        #pragma unroll
        for (int c = 0; c < 8; c++) {
            float4 ov;
            unpk2(ov.x, ov.y, o2[2 * c]);
            unpk2(ov.z, ov.w, o2[2 * c + 1]);
            ov.x = tf32r(ov.x); ov.y = tf32r(ov.y);
            ov.z = tf32r(ov.z); ov.w = tf32r(ov.w);
            Os4[tid * 8 + c] = ov;
        }
    }
    __syncthreads();

    float* obase = out + (size_t)bw * WIN * 512 + h * DH;
    for (int l = tid; l < WIN * 8; l += 64) {
        int i = l >> 3, c = l & 7;
        *((float4*)(obase + (size_t)i * 512) + c) = Os4[i * 8 + c];
    }
}

// --------------------------------- launcher --------------------------------
extern "C" void kernel_launch(void* const* d_in, const int* in_sizes, int n_in,
                              void* d_out, int out_size)
{
    const float* x          = (const float*)d_in[0];
    const float* w_qkv      = (const float*)d_in[1];
    const float* bias_table = (const float*)d_in[2];
    const float* w_out      = (const float*)d_in[3];
    float* out = (float*)d_out;

    float *qkv, *att, *xr, *wqkv_r, *wout_r;
    cudaGetSymbolAddress((void**)&qkv,    g_qkv);
    cudaGetSymbolAddress((void**)&att,    g_att);
    cudaGetSymbolAddress((void**)&xr,     g_xr);
    cudaGetSymbolAddress((void**)&wqkv_r, g_wqkv_r);
    cudaGetSymbolAddress((void**)&wout_r, g_wout_r);

    cudaFuncSetAttribute(gemm_tf32, cudaFuncAttributeMaxDynamicSharedMemorySize,
                         SMEM_FLOATS * 4);

    const long nreal = (long)M_REAL * 512;
    const long ntot  = (long)M_PAD  * 512;

    round_pad<<<(int)((ntot + 255) / 256), 256>>>(x, xr, nreal, ntot);
    round_copy<<<(786432 + 255) / 256, 256>>>(w_qkv, wqkv_r, 786432);
    round_copy<<<(262144 + 255) / 256, 256>>>(w_out, wout_r, 262144);
    zero_fill<<<(64 * 512 + 255) / 256, 256>>>(att + nreal, 64 * 512);

    // K1: qkv = xr @ wqkv_r
    gemm_tf32<<<dim3(1536 / BN, M_PAD / BM), 128, SMEM_FLOATS * 4>>>(
        xr, wqkv_r, qkv, M_REAL, 1536);

    // K2: attention
    attn_kernel<<<NWIN * HEADS, 64>>>(qkv, bias_table, att);

    // K3: out = att @ wout_r
    gemm_tf32<<<dim3(512 / BN, M_PAD / BM), 128, SMEM_FLOATS * 4>>>(
        att, wout_r, out, M_REAL, 512);
}